// round 8
// baseline (speedup 1.0000x reference)
#include <cuda_runtime.h>
#include <math.h>
#include <stdint.h>

#define LL 1024
#define NB 8
#define CC 1024
#define HH 16
#define HD 64
#define MM (LL*NB)          // 8192
#define C3 (3*CC)           // 3072
#define NHH (NB*HH)         // 128
#define LOGIT_MAX 4.605170185988091f
#define KIT 64              // K=1024 -> 64 k16 stages

// ---- scratch (device globals) ----
__device__ float g_qkv[(size_t)MM * C3];
__device__ float g_q[(size_t)NHH * LL * 128];  // fragment-order hi/lo (64 MB)
__device__ float g_k[(size_t)NHH * LL * 128];  // fragment-order hi/lo (64 MB)
__device__ float g_v[(size_t)NHH * LL * HD];   // fragment-order tf32
__device__ float g_xp[(size_t)MM * CC];    // packed x
__device__ float g_op[(size_t)MM * CC];    // packed attn-out (written by flash)
__device__ float g_w1p[(size_t)C3 * CC];   // packed in_proj_weight
__device__ float g_w2p[(size_t)CC * CC];   // packed out_w

__device__ __forceinline__ float tf32r(float x) {
    uint32_t u;
    asm("cvt.rna.tf32.f32 %0, %1;" : "=r"(u) : "f"(x));
    return __uint_as_float(u);
}
__device__ __forceinline__ uint32_t smem_u32(const void* p) {
    uint32_t a;
    asm("{ .reg .u64 t; cvta.to.shared.u64 t, %1; cvt.u32.u64 %0, t; }" : "=r"(a) : "l"(p));
    return a;
}
__device__ __forceinline__ void cp16(uint32_t dst, const void* src) {
    asm volatile("cp.async.cg.shared.global [%0], [%1], 16;" :: "r"(dst), "l"(src));
}
__device__ __forceinline__ void cp_commit() {
    asm volatile("cp.async.commit_group;");
}
__device__ __forceinline__ void cp_wait2() {
    asm volatile("cp.async.wait_group 2;");
}
__device__ __forceinline__ void cp_wait0() {
    asm volatile("cp.async.wait_group 0;");
}
__device__ __forceinline__ void mma_tf32_16x8x8(float* d, const uint32_t* a, const uint32_t* b) {
    asm volatile(
        "mma.sync.aligned.m16n8k8.row.col.f32.tf32.tf32.f32 "
        "{%0,%1,%2,%3}, {%4,%5,%6,%7}, {%8,%9}, {%0,%1,%2,%3};\n"
        : "+f"(d[0]), "+f"(d[1]), "+f"(d[2]), "+f"(d[3])
        : "r"(a[0]), "r"(a[1]), "r"(a[2]), "r"(a[3]), "r"(b[0]), "r"(b[1]));
}

// packed-A scalar index (for fused o-pack in flash epilogue)
__device__ __forceinline__ size_t pk_idx(int m, int k) {
    const int mb = m >> 7, mt = (m >> 4) & 7, gg = m & 7, h8 = (m >> 3) & 1;
    const int kb = k >> 4, c = (k >> 3) & 1, kq_ = k & 3, k4 = (k >> 2) & 1;
    return ((size_t)(mb * 64 + kb)) * 2048 + (c*8 + mt)*128 + (gg*4 + kq_)*4 + h8 + 2*k4;
}

// ============================================================
// Pack A [M x 1024] row-major -> fragment-order tf32 stages.
// ============================================================
__global__ __launch_bounds__(256)
void pack_a(const float* __restrict__ src, float* __restrict__ dst) {
    const size_t d = (size_t)blockIdx.x * 256 + threadIdx.x;
    const int fi   = (int)(d & 511);
    const size_t sid = d >> 9;
    const int mb = (int)(sid >> 6);
    const int kb = (int)(sid & 63);
    const int c  = fi >> 8;
    const int mt = (fi >> 5) & 7;
    const int lane = fi & 31;
    const int g  = lane >> 2;
    const int kq = lane & 3;
    const int r0 = mb*128 + mt*16 + g;
    const int k0 = kb*16 + c*8 + kq;
    float4 o;
    o.x = tf32r(src[(size_t)r0      * 1024 + k0]);
    o.y = tf32r(src[(size_t)(r0+8)  * 1024 + k0]);
    o.z = tf32r(src[(size_t)r0      * 1024 + k0 + 4]);
    o.w = tf32r(src[(size_t)(r0+8)  * 1024 + k0 + 4]);
    reinterpret_cast<float4*>(dst)[d] = o;
}

// ============================================================
// Pack B [N x 1024] row-major -> fragment-order tf32 stages.
// ============================================================
__global__ __launch_bounds__(256)
void pack_b(const float* __restrict__ src, float* __restrict__ dst) {
    const size_t d = (size_t)blockIdx.x * 256 + threadIdx.x;
    const int fi   = (int)(d & 1023);
    const size_t sid = d >> 10;
    const int nb = (int)(sid >> 6);
    const int kb = (int)(sid & 63);
    const int c  = fi >> 9;
    const int nt = (fi >> 5) & 15;
    const int lane = fi & 31;
    const int g  = lane >> 2;
    const int kq = lane & 3;
    const int col = nb*128 + nt*8 + g;
    const int k0  = kb*16 + c*8 + kq;
    float2 o;
    o.x = tf32r(src[(size_t)col * 1024 + k0]);
    o.y = tf32r(src[(size_t)col * 1024 + k0 + 4]);
    reinterpret_cast<float2*>(dst)[d] = o;
}

// ============================================================
// tf32 mma.sync GEMM on packed operands (unchanged, passing).
// ============================================================
#define GEMM_SMEM (4*4096*4)

__global__ __launch_bounds__(256, 2)
void gemm_tf32_pk(const float* __restrict__ Ap, const float* __restrict__ Bp,
                  const float* __restrict__ bias, float* __restrict__ C,
                  int Ncols) {
    extern __shared__ float sm[];
    const uint32_t smb = smem_u32(sm);
    const int t  = threadIdx.x;
    const int wid  = t >> 5;
    const int lane = t & 31;
    const int g  = lane >> 2;
    const int kq = lane & 3;
    const int wm4 = (wid >> 2) * 4;
    const int wn8 = (wid & 3) * 4;
    const int m0 = blockIdx.y * 128;
    const int n0 = blockIdx.x * 128;

    const float* Ab = Ap + (size_t)blockIdx.y * KIT * 2048;
    const float* Bb = Bp + (size_t)blockIdx.x * KIT * 2048;

    float acc[4][4][4] = {};

    #define ISSUE(j)                                                        \
    {                                                                       \
        const uint32_t sb = smb + ((j) & 3) * 16384;                        \
        const float* ag = Ab + (size_t)(j) * 2048;                          \
        const float* bg = Bb + (size_t)(j) * 2048;                          \
        cp16(sb +            t*16, ag + t*4);                               \
        cp16(sb +  4096    + t*16, ag + 1024 + t*4);                        \
        cp16(sb +  8192    + t*16, bg + t*4);                               \
        cp16(sb + 12288    + t*16, bg + 1024 + t*4);                        \
    }

    ISSUE(0); cp_commit();
    ISSUE(1); cp_commit();
    ISSUE(2); cp_commit();

    for (int i = 0; i < KIT; i++) {
        cp_wait2();
        __syncthreads();
        const float* as = sm + (i & 3) * 4096;
        const float* bs = as + 2048;
        #pragma unroll
        for (int c = 0; c < 2; c++) {
            uint32_t a[4][4], b[4][2];
            #pragma unroll
            for (int ti = 0; ti < 4; ti++) {
                float4 af = *reinterpret_cast<const float4*>(
                    &as[(c*8 + wm4 + ti)*128 + lane*4]);
                a[ti][0] = __float_as_uint(af.x);
                a[ti][1] = __float_as_uint(af.y);
                a[ti][2] = __float_as_uint(af.z);
                a[ti][3] = __float_as_uint(af.w);
            }
            #pragma unroll
            for (int j = 0; j < 4; j++) {
                float2 bf = *reinterpret_cast<const float2*>(
                    &bs[(c*16 + wn8 + j)*64 + lane*2]);
                b[j][0] = __float_as_uint(bf.x);
                b[j][1] = __float_as_uint(bf.y);
            }
            #pragma unroll
            for (int ti = 0; ti < 4; ti++)
                #pragma unroll
                for (int j = 0; j < 4; j++)
                    mma_tf32_16x8x8(acc[ti][j], a[ti], b[j]);
        }
        const int jn = i + 3;
        if (jn < KIT) ISSUE(jn);
        cp_commit();
    }
    #undef ISSUE

    #pragma unroll
    for (int ti = 0; ti < 4; ti++) {
        const int r0 = m0 + wm4*16 + ti*16 + g;
        #pragma unroll
        for (int j = 0; j < 4; j++) {
            const int c0 = n0 + wn8*8 + j*8 + 2*kq;
            const float bx = bias[c0], by = bias[c0+1];
            float2 lo, hi;
            lo.x = acc[ti][j][0] + bx; lo.y = acc[ti][j][1] + by;
            hi.x = acc[ti][j][2] + bx; hi.y = acc[ti][j][3] + by;
            *reinterpret_cast<float2*>(&C[(size_t)r0 * Ncols + c0]) = lo;
            *reinterpret_cast<float2*>(&C[(size_t)(r0+8) * Ncols + c0]) = hi;
        }
    }
}

// ============================================================
// Normalize + scatter into FLASH FRAGMENT ORDER.
// Q stage (nh,qt) 8192 floats: float4 slot ((w*8+kb)*2+hl)*32 + g*4+kq
//   = {hi/lo of Q[rA][k], Q[rB][k], Q[rA][k+4], Q[rB][k+4]}, rA=w*16+g.
// K stage (nh,kt) 8192: float4 slot (kb*8+j)*32 + g*4+kq
//   = {Khi[col][k], Klo[col][k], Khi[col][k+4], Klo[col][k+4]}, col=j*8+g.
// V stage (nh,kt) 4096: float2 slot (kkb*8+j)*32 + g*4+kq
//   = {V[key][d], V[key+4][d]}, d=j*8+g, key=kkb*8+kq.
// ============================================================
__global__ __launch_bounds__(256)
void norm_scatter_kernel(const float* __restrict__ logit_scale) {
    const int warp = (blockIdx.x * blockDim.x + threadIdx.x) >> 5;
    const int lane = threadIdx.x & 31;
    const int tsel = warp / (NHH * LL);
    const int rr   = warp - tsel * (NHH * LL);
    const int nh   = rr >> 10;
    const int l    = rr & 1023;
    const int n    = nh >> 4;
    const int h    = nh & 15;
    const size_t src = (size_t)(l * NB + n) * C3 + (size_t)tsel * CC + h * HD;
    float v0 = g_qkv[src + lane];
    float v1 = g_qkv[src + lane + 32];

    if (tsel == 2) {
        // V fragment scatter
        const size_t base = ((size_t)(nh*16 + (l >> 6))) * 4096;
        const int key = l & 63;
        const int kkb = key >> 3, kqv = key & 3, k4v = (key >> 2) & 1;
        #pragma unroll
        for (int e = 0; e < 2; e++) {
            const int d = lane + 32*e;
            const int j = d >> 3, gj = d & 7;
            g_v[base + (size_t)((kkb*8 + j)*32 + gj*4 + kqv)*2 + k4v] =
                tf32r(e ? v1 : v0);
        }
        return;
    }

    float s = v0*v0 + v1*v1;
    #pragma unroll
    for (int o = 16; o > 0; o >>= 1) s += __shfl_xor_sync(0xffffffffu, s, o);
    float inv = 1.0f / fmaxf(sqrtf(s), 1e-12f);
    if (tsel == 0) inv *= expf(fminf(logit_scale[h], LOGIT_MAX));
    v0 *= inv; v1 *= inv;

    const size_t base = ((size_t)(nh*16 + (l >> 6))) * 8192;
    if (tsel == 0) {
        const int r = l & 63;
        const int w = r >> 4, gq = r & 7, hb = (r >> 3) & 1;
        #pragma unroll
        for (int e = 0; e < 2; e++) {
            const float v = e ? v1 : v0;
            const int d = lane + 32*e;
            const int kb = d >> 3, kq = d & 3, k4 = (d >> 2) & 1;
            const float hi = tf32r(v);
            const float lo = tf32r(v - hi);
            const size_t sl = base + (size_t)(((w*8 + kb)*2)*32 + gq*4 + kq)*4 + hb + 2*k4;
            g_q[sl]        = hi;      // hl=0 plane
            g_q[sl + 128]  = lo;      // hl=1 plane (+32 float4s = +128 floats)
        }
    } else {
        const int c0 = l & 63;
        const int j = c0 >> 3, gj = c0 & 7;
        #pragma unroll
        for (int e = 0; e < 2; e++) {
            const float v = e ? v1 : v0;
            const int d = lane + 32*e;
            const int kb = d >> 3, kq = d & 3, k4 = (d >> 2) & 1;
            const float hi = tf32r(v);
            const float lo = tf32r(v - hi);
            const size_t sl = base + (size_t)((kb*8 + j)*32 + gj*4 + kq)*4 + 2*k4;
            g_k[sl]     = hi;
            g_k[sl + 1] = lo;
        }
    }
}

// ============================================================
// Flash attention, tf32 mma, fragment-order operands.
// Smem = direct image of gmem stages (no padding, conflict-free).
// Epilogue writes g_op in GEMM-packed order (fused o-pack).
// ============================================================
#define FL_Q 0
#define FL_K 8192
#define FL_V 16384
#define FL_P 20480
#define PSTR  72
#define FLASH_SMEM ((20480 + 64*PSTR) * (int)sizeof(float))   // 100352 B

__global__ __launch_bounds__(128, 2)
void flash_attn_mma(const float* __restrict__ head_scale) {
    extern __shared__ float smf[];
    float* Qs = smf + FL_Q;
    float* Ks = smf + FL_K;
    float* Vs = smf + FL_V;
    float* Ps = smf + FL_P;
    const uint32_t smb  = smem_u32(smf);
    const uint32_t smbQ = smb + FL_Q * 4;
    const uint32_t smbK = smb + FL_K * 4;
    const uint32_t smbV = smb + FL_V * 4;

    const int t    = threadIdx.x;
    const int w    = t >> 5;
    const int lane = t & 31;
    const int g    = lane >> 2;
    const int kq   = lane & 3;
    const int nh = blockIdx.y;
    const int qt = blockIdx.x;
    const float* Qg = g_q + ((size_t)(nh*16 + qt)) * 8192;
    const float* Kg = g_k + ((size_t)nh * 16) * 8192;
    const float* Vg = g_v + ((size_t)nh * 16) * 4096;

    for (int i = t; i < 2048; i += 128)
        cp16(smbQ + i*16, Qg + i*4);

    float acc[8][4] = {};
    float miA = -1e30f, miB = -1e30f, liA = 0.0f, liB = 0.0f;

    const int rA = w*16 + g;
    const int rB = rA + 8;

    for (int kt = 0; kt < 16; kt++) {
        const float* Kt = Kg + (size_t)kt * 8192;
        const float* Vt = Vg + (size_t)kt * 4096;
        for (int i = t; i < 2048; i += 128)
            cp16(smbK + i*16, Kt + i*4);
        for (int i = t; i < 1024; i += 128)
            cp16(smbV + i*16, Vt + i*4);
        cp_commit();
        cp_wait0();
        __syncthreads();

        // ---- S = Q @ K^T (3xTF32) ----
        float sd[8][4] = {};
        #pragma unroll
        for (int kb = 0; kb < 8; kb++) {
            float4 fh = *reinterpret_cast<const float4*>(
                &Qs[((w*8 + kb)*2 + 0)*128 + lane*4]);
            float4 fl = *reinterpret_cast<const float4*>(
                &Qs[((w*8 + kb)*2 + 1)*128 + lane*4]);
            uint32_t ahi[4] = {__float_as_uint(fh.x), __float_as_uint(fh.y),
                               __float_as_uint(fh.z), __float_as_uint(fh.w)};
            uint32_t alo[4] = {__float_as_uint(fl.x), __float_as_uint(fl.y),
                               __float_as_uint(fl.z), __float_as_uint(fl.w)};
            #pragma unroll
            for (int j = 0; j < 8; j++) {
                float4 fb = *reinterpret_cast<const float4*>(
                    &Ks[(kb*8 + j)*128 + lane*4]);
                uint32_t bhi[2] = {__float_as_uint(fb.x), __float_as_uint(fb.z)};
                uint32_t blo[2] = {__float_as_uint(fb.y), __float_as_uint(fb.w)};
                mma_tf32_16x8x8(sd[j], ahi, bhi);
                mma_tf32_16x8x8(sd[j], ahi, blo);
                mma_tf32_16x8x8(sd[j], alo, bhi);
            }
        }

        // ---- online softmax ----
        float rmA = -1e30f, rmB = -1e30f;
        #pragma unroll
        for (int j = 0; j < 8; j++) {
            rmA = fmaxf(rmA, fmaxf(sd[j][0], sd[j][1]));
            rmB = fmaxf(rmB, fmaxf(sd[j][2], sd[j][3]));
        }
        rmA = fmaxf(rmA, __shfl_xor_sync(0xffffffffu, rmA, 1));
        rmA = fmaxf(rmA, __shfl_xor_sync(0xffffffffu, rmA, 2));
        rmB = fmaxf(rmB, __shfl_xor_sync(0xffffffffu, rmB, 1));
        rmB = fmaxf(rmB, __shfl_xor_sync(0xffffffffu, rmB, 2));
        float mA = fmaxf(miA, rmA), mB = fmaxf(miB, rmB);
        float corrA = __expf(miA - mA), corrB = __expf(miB - mB);
        float sumA = 0.0f, sumB = 0.0f;
        #pragma unroll
        for (int j = 0; j < 8; j++) {
            float p0 = __expf(sd[j][0] - mA);
            float p1 = __expf(sd[j][1] - mA);
            float p2 = __expf(sd[j][2] - mB);
            float p3 = __expf(sd[j][3] - mB);
            sumA += p0 + p1;
            sumB += p2 + p3;
            *reinterpret_cast<float2*>(&Ps[rA*PSTR + j*8 + 2*kq]) =
                make_float2(tf32r(p0), tf32r(p1));
            *reinterpret_cast<float2*>(&Ps[rB*PSTR + j*8 + 2*kq]) =
                make_float2(tf32r(p2), tf32r(p3));
            acc[j][0] *= corrA; acc[j][1] *= corrA;
            acc[j][2] *= corrB; acc[j][3] *= corrB;
        }
        sumA += __shfl_xor_sync(0xffffffffu, sumA, 1);
        sumA += __shfl_xor_sync(0xffffffffu, sumA, 2);
        sumB += __shfl_xor_sync(0xffffffffu, sumB, 1);
        sumB += __shfl_xor_sync(0xffffffffu, sumB, 2);
        liA = liA * corrA + sumA;  miA = mA;
        liB = liB * corrB + sumB;  miB = mB;
        __syncwarp();

        // ---- O += P @ V (single tf32) ----
        #pragma unroll
        for (int kb = 0; kb < 8; kb++) {
            uint32_t pa[4];
            pa[0] = __float_as_uint(Ps[rA*PSTR + kb*8+kq]);
            pa[1] = __float_as_uint(Ps[rB*PSTR + kb*8+kq]);
            pa[2] = __float_as_uint(Ps[rA*PSTR + kb*8+kq+4]);
            pa[3] = __float_as_uint(Ps[rB*PSTR + kb*8+kq+4]);
            #pragma unroll
            for (int j = 0; j < 8; j++) {
                float2 fv = *reinterpret_cast<const float2*>(
                    &Vs[((kb*8 + j)*32 + lane)*2]);
                uint32_t vb[2] = {__float_as_uint(fv.x), __float_as_uint(fv.y)};
                mma_tf32_16x8x8(acc[j], pa, vb);
            }
        }
        __syncthreads();
    }

    // ---- epilogue: write g_op directly in GEMM-packed order ----
    const int h = nh & 15;
    const int n = nh >> 4;
    const float hs = head_scale[h];
    const float sAf = hs / liA, sBf = hs / liB;
    const int mA = (qt*64 + rA)*NB + n;
    const int mB = (qt*64 + rB)*NB + n;
    #pragma unroll
    for (int j = 0; j < 8; j++) {
        const int c0 = h*HD + j*8 + 2*kq;
        g_op[pk_idx(mA, c0)]   = tf32r(acc[j][0]*sAf);
        g_op[pk_idx(mA, c0+1)] = tf32r(acc[j][1]*sAf);
        g_op[pk_idx(mB, c0)]   = tf32r(acc[j][2]*sBf);
        g_op[pk_idx(mB, c0+1)] = tf32r(acc[j][3]*sBf);
    }
}

// ============================================================
extern "C" void kernel_launch(void* const* d_in, const int* in_sizes, int n_in,
                              void* d_out, int out_size) {
    const float* x           = (const float*)d_in[0];
    const float* w_in        = (const float*)d_in[1];
    const float* b_in        = (const float*)d_in[2];
    const float* logit_scale = (const float*)d_in[3];
    const float* head_scale  = (const float*)d_in[4];
    const float* out_w       = (const float*)d_in[5];
    const float* out_b       = (const float*)d_in[6];
    float* out = (float*)d_out;

    float *qkv_p, *xp_p, *op_p, *w1p_p, *w2p_p;
    cudaGetSymbolAddress((void**)&qkv_p, g_qkv);
    cudaGetSymbolAddress((void**)&xp_p,  g_xp);
    cudaGetSymbolAddress((void**)&op_p,  g_op);
    cudaGetSymbolAddress((void**)&w1p_p, g_w1p);
    cudaGetSymbolAddress((void**)&w2p_p, g_w2p);

    cudaFuncSetAttribute(flash_attn_mma,
                         cudaFuncAttributeMaxDynamicSharedMemorySize, FLASH_SMEM);
    cudaFuncSetAttribute(gemm_tf32_pk,
                         cudaFuncAttributeMaxDynamicSharedMemorySize, GEMM_SMEM);

    pack_a<<<MM, 256>>>(x, xp_p);
    pack_b<<<C3*2, 256>>>(w_in, w1p_p);
    pack_b<<<CC*2, 256>>>(out_w, w2p_p);

    // 1) qkv = x @ W^T + b
    gemm_tf32_pk<<<dim3(C3/128, MM/128), 256, GEMM_SMEM>>>(xp_p, w1p_p, b_in, qkv_p, C3);
    // 2) normalize + fragment-order scatter
    norm_scatter_kernel<<<(3*NHH*LL)/8, 256>>>(logit_scale);
    // 3) flash attention (writes packed o directly)
    flash_attn_mma<<<dim3(LL/64, NHH), 128, FLASH_SMEM>>>(head_scale);
    // 4) out = o @ out_w^T + out_b
    gemm_tf32_pk<<<dim3(CC/128, MM/128), 256, GEMM_SMEM>>>(op_p, w2p_p, out_b, out, CC);
}

// round 9
// speedup vs baseline: 1.3592x; 1.3592x over previous
#include <cuda_runtime.h>
#include <math.h>
#include <stdint.h>

#define LL 1024
#define NB 8
#define CC 1024
#define HH 16
#define HD 64
#define MM (LL*NB)          // 8192
#define C3 (3*CC)           // 3072
#define NHH (NB*HH)         // 128
#define LOGIT_MAX 4.605170185988091f
#define KIT 64              // K=1024 -> 64 k16 stages

// ---- scratch (device globals) ----
__device__ float g_qkv[(size_t)MM * C3];
__device__ float g_q[(size_t)NHH * LL * 128];  // hi/lo interleaved rows
__device__ float g_k[(size_t)NHH * LL * 128];  // hi/lo interleaved rows
__device__ float g_v[(size_t)NHH * LL * HD];   // tf32-rounded
__device__ float g_o[(size_t)MM * CC];
__device__ float g_xp[(size_t)MM * CC];    // packed x
__device__ float g_op[(size_t)MM * CC];    // packed attn-out
__device__ float g_w1p[(size_t)C3 * CC];   // packed in_proj_weight
__device__ float g_w2p[(size_t)CC * CC];   // packed out_w

__device__ __forceinline__ float tf32r(float x) {
    uint32_t u;
    asm("cvt.rna.tf32.f32 %0, %1;" : "=r"(u) : "f"(x));
    return __uint_as_float(u);
}
__device__ __forceinline__ uint32_t smem_u32(const void* p) {
    uint32_t a;
    asm("{ .reg .u64 t; cvta.to.shared.u64 t, %1; cvt.u32.u64 %0, t; }" : "=r"(a) : "l"(p));
    return a;
}
__device__ __forceinline__ void cp16(uint32_t dst, const void* src) {
    asm volatile("cp.async.cg.shared.global [%0], [%1], 16;" :: "r"(dst), "l"(src));
}
__device__ __forceinline__ void cp_commit() {
    asm volatile("cp.async.commit_group;");
}
__device__ __forceinline__ void cp_wait2() {
    asm volatile("cp.async.wait_group 2;");
}
__device__ __forceinline__ void cp_wait1() {
    asm volatile("cp.async.wait_group 1;");
}
__device__ __forceinline__ void mma_tf32_16x8x8(float* d, const uint32_t* a, const uint32_t* b) {
    asm volatile(
        "mma.sync.aligned.m16n8k8.row.col.f32.tf32.tf32.f32 "
        "{%0,%1,%2,%3}, {%4,%5,%6,%7}, {%8,%9}, {%0,%1,%2,%3};\n"
        : "+f"(d[0]), "+f"(d[1]), "+f"(d[2]), "+f"(d[3])
        : "r"(a[0]), "r"(a[1]), "r"(a[2]), "r"(a[3]), "r"(b[0]), "r"(b[1]));
}

// ============================================================
// Pack A [M x 1024] row-major -> fragment-order tf32 stages.
// ============================================================
__global__ __launch_bounds__(256)
void pack_a(const float* __restrict__ src, float* __restrict__ dst) {
    const size_t d = (size_t)blockIdx.x * 256 + threadIdx.x;
    const int fi   = (int)(d & 511);
    const size_t sid = d >> 9;
    const int mb = (int)(sid >> 6);
    const int kb = (int)(sid & 63);
    const int c  = fi >> 8;
    const int mt = (fi >> 5) & 7;
    const int lane = fi & 31;
    const int g  = lane >> 2;
    const int kq = lane & 3;
    const int r0 = mb*128 + mt*16 + g;
    const int k0 = kb*16 + c*8 + kq;
    float4 o;
    o.x = tf32r(src[(size_t)r0      * 1024 + k0]);
    o.y = tf32r(src[(size_t)(r0+8)  * 1024 + k0]);
    o.z = tf32r(src[(size_t)r0      * 1024 + k0 + 4]);
    o.w = tf32r(src[(size_t)(r0+8)  * 1024 + k0 + 4]);
    reinterpret_cast<float4*>(dst)[d] = o;
}

// ============================================================
// Pack B [N x 1024] row-major -> fragment-order tf32 stages.
// ============================================================
__global__ __launch_bounds__(256)
void pack_b(const float* __restrict__ src, float* __restrict__ dst) {
    const size_t d = (size_t)blockIdx.x * 256 + threadIdx.x;
    const int fi   = (int)(d & 1023);
    const size_t sid = d >> 10;
    const int nb = (int)(sid >> 6);
    const int kb = (int)(sid & 63);
    const int c  = fi >> 9;
    const int nt = (fi >> 5) & 15;
    const int lane = fi & 31;
    const int g  = lane >> 2;
    const int kq = lane & 3;
    const int col = nb*128 + nt*8 + g;
    const int k0  = kb*16 + c*8 + kq;
    float2 o;
    o.x = tf32r(src[(size_t)col * 1024 + k0]);
    o.y = tf32r(src[(size_t)col * 1024 + k0 + 4]);
    reinterpret_cast<float2*>(dst)[d] = o;
}

// ============================================================
// tf32 mma.sync GEMM on packed operands (unchanged, passing).
// ============================================================
#define GEMM_SMEM (4*4096*4)

__global__ __launch_bounds__(256, 2)
void gemm_tf32_pk(const float* __restrict__ Ap, const float* __restrict__ Bp,
                  const float* __restrict__ bias, float* __restrict__ C,
                  int Ncols) {
    extern __shared__ float sm[];
    const uint32_t smb = smem_u32(sm);
    const int t  = threadIdx.x;
    const int wid  = t >> 5;
    const int lane = t & 31;
    const int g  = lane >> 2;
    const int kq = lane & 3;
    const int wm4 = (wid >> 2) * 4;
    const int wn8 = (wid & 3) * 4;
    const int m0 = blockIdx.y * 128;
    const int n0 = blockIdx.x * 128;

    const float* Ab = Ap + (size_t)blockIdx.y * KIT * 2048;
    const float* Bb = Bp + (size_t)blockIdx.x * KIT * 2048;

    float acc[4][4][4] = {};

    #define ISSUE(j)                                                        \
    {                                                                       \
        const uint32_t sb = smb + ((j) & 3) * 16384;                        \
        const float* ag = Ab + (size_t)(j) * 2048;                          \
        const float* bg = Bb + (size_t)(j) * 2048;                          \
        cp16(sb +            t*16, ag + t*4);                               \
        cp16(sb +  4096    + t*16, ag + 1024 + t*4);                        \
        cp16(sb +  8192    + t*16, bg + t*4);                               \
        cp16(sb + 12288    + t*16, bg + 1024 + t*4);                        \
    }

    ISSUE(0); cp_commit();
    ISSUE(1); cp_commit();
    ISSUE(2); cp_commit();

    for (int i = 0; i < KIT; i++) {
        cp_wait2();
        __syncthreads();
        const float* as = sm + (i & 3) * 4096;
        const float* bs = as + 2048;
        #pragma unroll
        for (int c = 0; c < 2; c++) {
            uint32_t a[4][4], b[4][2];
            #pragma unroll
            for (int ti = 0; ti < 4; ti++) {
                float4 af = *reinterpret_cast<const float4*>(
                    &as[(c*8 + wm4 + ti)*128 + lane*4]);
                a[ti][0] = __float_as_uint(af.x);
                a[ti][1] = __float_as_uint(af.y);
                a[ti][2] = __float_as_uint(af.z);
                a[ti][3] = __float_as_uint(af.w);
            }
            #pragma unroll
            for (int j = 0; j < 4; j++) {
                float2 bf = *reinterpret_cast<const float2*>(
                    &bs[(c*16 + wn8 + j)*64 + lane*2]);
                b[j][0] = __float_as_uint(bf.x);
                b[j][1] = __float_as_uint(bf.y);
            }
            #pragma unroll
            for (int ti = 0; ti < 4; ti++)
                #pragma unroll
                for (int j = 0; j < 4; j++)
                    mma_tf32_16x8x8(acc[ti][j], a[ti], b[j]);
        }
        const int jn = i + 3;
        if (jn < KIT) ISSUE(jn);
        cp_commit();
    }
    #undef ISSUE

    #pragma unroll
    for (int ti = 0; ti < 4; ti++) {
        const int r0 = m0 + wm4*16 + ti*16 + g;
        #pragma unroll
        for (int j = 0; j < 4; j++) {
            const int c0 = n0 + wn8*8 + j*8 + 2*kq;
            const float bx = bias[c0], by = bias[c0+1];
            float2 lo, hi;
            lo.x = acc[ti][j][0] + bx; lo.y = acc[ti][j][1] + by;
            hi.x = acc[ti][j][2] + bx; hi.y = acc[ti][j][3] + by;
            *reinterpret_cast<float2*>(&C[(size_t)r0 * Ncols + c0]) = lo;
            *reinterpret_cast<float2*>(&C[(size_t)(r0+8) * Ncols + c0]) = hi;
        }
    }
}

// ============================================================
// Normalize + scatter (R7 version: coalesced float2 row writes).
// ============================================================
__global__ __launch_bounds__(256)
void norm_scatter_kernel(const float* __restrict__ logit_scale) {
    const int warp = (blockIdx.x * blockDim.x + threadIdx.x) >> 5;
    const int lane = threadIdx.x & 31;
    const int tsel = warp / (NHH * LL);
    const int rr   = warp - tsel * (NHH * LL);
    const int nh   = rr >> 10;
    const int l    = rr & 1023;
    const int n    = nh >> 4;
    const int h    = nh & 15;
    const size_t src = (size_t)(l * NB + n) * C3 + (size_t)tsel * CC + h * HD;
    float v0 = g_qkv[src + lane];
    float v1 = g_qkv[src + lane + 32];
    if (tsel < 2) {
        float s = v0*v0 + v1*v1;
        #pragma unroll
        for (int o = 16; o > 0; o >>= 1) s += __shfl_xor_sync(0xffffffffu, s, o);
        float inv = 1.0f / fmaxf(sqrtf(s), 1e-12f);
        if (tsel == 0) inv *= expf(fminf(logit_scale[h], LOGIT_MAX));
        v0 *= inv; v1 *= inv;
        float h0 = tf32r(v0), h1 = tf32r(v1);
        float2* dst = reinterpret_cast<float2*>(tsel == 0 ? g_q : g_k)
                      + ((size_t)nh * LL + l) * 64;
        dst[lane]      = make_float2(h0, tf32r(v0 - h0));
        dst[lane + 32] = make_float2(h1, tf32r(v1 - h1));
    } else {
        const size_t o = ((size_t)nh * LL + l) * HD;
        g_v[o + lane]      = tf32r(v0);
        g_v[o + lane + 32] = tf32r(v1);
    }
}

// ============================================================
// Flash attention, tf32 mma, cp.async loader (R7 layout) with
// single-buffer K/V software pipeline: every wait is wait_group(1);
// K_{t+1} copies overlap V-wait+PV, V_{t+1} copies overlap next S.
// ============================================================
#define QKSTR 132
#define VSTR  72
#define PSTR  72
#define FL_Q 0
#define FL_K (64*QKSTR)
#define FL_V (2*64*QKSTR)
#define FL_P (2*64*QKSTR + 64*VSTR)
#define FLASH_SMEM ((2*64*QKSTR + 64*VSTR + 64*PSTR) * (int)sizeof(float))

__global__ __launch_bounds__(128, 2)
void flash_attn_mma(const float* __restrict__ head_scale) {
    extern __shared__ float smf[];
    float* Qs = smf + FL_Q;
    float* Ks = smf + FL_K;
    float* Vs = smf + FL_V;
    float* Ps = smf + FL_P;
    const uint32_t smbQ = smem_u32(smf) + FL_Q * 4;
    const uint32_t smbK = smem_u32(smf) + FL_K * 4;
    const uint32_t smbV = smem_u32(smf) + FL_V * 4;

    const int t    = threadIdx.x;
    const int w    = t >> 5;
    const int lane = t & 31;
    const int g    = lane >> 2;
    const int kq   = lane & 3;
    const int nh = blockIdx.y;
    const int qt = blockIdx.x;
    const float* Qg = g_q + ((size_t)nh * LL + qt * 64) * 128;
    const float* Kg = g_k + (size_t)nh * LL * 128;
    const float* Vg = g_v + (size_t)nh * LL * HD;

    #define ISSUE_K(kt)                                                     \
    {                                                                       \
        const float* Kt = Kg + (size_t)(kt) * 64 * 128;                     \
        for (int i = t; i < 2048; i += 128) {                               \
            int r = i >> 5, c = i & 31;                                     \
            cp16(smbK + r*(QKSTR*4) + c*16, Kt + r*128 + c*4);              \
        }                                                                   \
    }
    #define ISSUE_V(kt)                                                     \
    {                                                                       \
        const float* Vt = Vg + (size_t)(kt) * 64 * 64;                      \
        for (int i = t; i < 1024; i += 128) {                               \
            int r = i >> 4, c = i & 15;                                     \
            cp16(smbV + r*(VSTR*4) + c*16, Vt + r*64 + c*4);                \
        }                                                                   \
    }

    // preload: Q | K0 | V0 as three groups
    for (int i = t; i < 2048; i += 128) {
        int r = i >> 5, c = i & 31;
        cp16(smbQ + r*(QKSTR*4) + c*16, Qg + r*128 + c*4);
    }
    cp_commit();
    ISSUE_K(0); cp_commit();
    ISSUE_V(0); cp_commit();

    float acc[8][4] = {};
    float miA = -1e30f, miB = -1e30f, liA = 0.0f, liB = 0.0f;

    const int rA = w*16 + g;
    const int rB = rA + 8;

    for (int kt = 0; kt < 16; kt++) {
        // K_kt (and Q) ready; V_kt may still be in flight
        cp_wait1();
        __syncthreads();

        // ---- S = Q @ K^T (3xTF32) ----
        float sd[8][4] = {};
        #pragma unroll
        for (int kb = 0; kb < 8; kb++) {
            const float2* qr0 = reinterpret_cast<const float2*>(&Qs[rA*QKSTR]);
            const float2* qr1 = reinterpret_cast<const float2*>(&Qs[rB*QKSTR]);
            float2 a0 = qr0[kb*8+kq],   a1 = qr1[kb*8+kq];
            float2 a2 = qr0[kb*8+kq+4], a3 = qr1[kb*8+kq+4];
            uint32_t ahi[4] = {__float_as_uint(a0.x), __float_as_uint(a1.x),
                               __float_as_uint(a2.x), __float_as_uint(a3.x)};
            uint32_t alo[4] = {__float_as_uint(a0.y), __float_as_uint(a1.y),
                               __float_as_uint(a2.y), __float_as_uint(a3.y)};
            #pragma unroll
            for (int j = 0; j < 8; j++) {
                const float2* kr = reinterpret_cast<const float2*>(&Ks[(j*8+g)*QKSTR]);
                float2 b0 = kr[kb*8+kq], b1 = kr[kb*8+kq+4];
                uint32_t bhi[2] = {__float_as_uint(b0.x), __float_as_uint(b1.x)};
                uint32_t blo[2] = {__float_as_uint(b0.y), __float_as_uint(b1.y)};
                mma_tf32_16x8x8(sd[j], ahi, bhi);
                mma_tf32_16x8x8(sd[j], ahi, blo);
                mma_tf32_16x8x8(sd[j], alo, bhi);
            }
        }

        // ---- online softmax ----
        float rmA = -1e30f, rmB = -1e30f;
        #pragma unroll
        for (int j = 0; j < 8; j++) {
            rmA = fmaxf(rmA, fmaxf(sd[j][0], sd[j][1]));
            rmB = fmaxf(rmB, fmaxf(sd[j][2], sd[j][3]));
        }
        rmA = fmaxf(rmA, __shfl_xor_sync(0xffffffffu, rmA, 1));
        rmA = fmaxf(rmA, __shfl_xor_sync(0xffffffffu, rmA, 2));
        rmB = fmaxf(rmB, __shfl_xor_sync(0xffffffffu, rmB, 1));
        rmB = fmaxf(rmB, __shfl_xor_sync(0xffffffffu, rmB, 2));
        float mA = fmaxf(miA, rmA), mB = fmaxf(miB, rmB);
        float corrA = __expf(miA - mA), corrB = __expf(miB - mB);
        float sumA = 0.0f, sumB = 0.0f;
        #pragma unroll
        for (int j = 0; j < 8; j++) {
            float p0 = __expf(sd[j][0] - mA);
            float p1 = __expf(sd[j][1] - mA);
            float p2 = __expf(sd[j][2] - mB);
            float p3 = __expf(sd[j][3] - mB);
            sumA += p0 + p1;
            sumB += p2 + p3;
            *reinterpret_cast<float2*>(&Ps[rA*PSTR + j*8 + 2*kq]) =
                make_float2(tf32r(p0), tf32r(p1));
            *reinterpret_cast<float2*>(&Ps[rB*PSTR + j*8 + 2*kq]) =
                make_float2(tf32r(p2), tf32r(p3));
            acc[j][0] *= corrA; acc[j][1] *= corrA;
            acc[j][2] *= corrB; acc[j][3] *= corrB;
        }
        sumA += __shfl_xor_sync(0xffffffffu, sumA, 1);
        sumA += __shfl_xor_sync(0xffffffffu, sumA, 2);
        sumB += __shfl_xor_sync(0xffffffffu, sumB, 1);
        sumB += __shfl_xor_sync(0xffffffffu, sumB, 2);
        liA = liA * corrA + sumA;  miA = mA;
        liB = liB * corrB + sumB;  miB = mB;

        // Ks dead in all warps -> start K_{kt+1} copy (overlaps V-wait + PV)
        __syncthreads();
        if (kt + 1 < 16) ISSUE_K(kt + 1);
        cp_commit();

        // V_kt ready
        cp_wait1();
        __syncthreads();

        // ---- O += P @ V (single tf32) ----
        #pragma unroll
        for (int kb = 0; kb < 8; kb++) {
            uint32_t pa[4];
            pa[0] = __float_as_uint(Ps[rA*PSTR + kb*8+kq]);
            pa[1] = __float_as_uint(Ps[rB*PSTR + kb*8+kq]);
            pa[2] = __float_as_uint(Ps[rA*PSTR + kb*8+kq+4]);
            pa[3] = __float_as_uint(Ps[rB*PSTR + kb*8+kq+4]);
            #pragma unroll
            for (int j = 0; j < 8; j++) {
                uint32_t vb[2];
                vb[0] = __float_as_uint(Vs[(kb*8+kq)*VSTR   + j*8+g]);
                vb[1] = __float_as_uint(Vs[(kb*8+kq+4)*VSTR + j*8+g]);
                mma_tf32_16x8x8(acc[j], pa, vb);
            }
        }

        // Vs dead in all warps -> start V_{kt+1} copy (overlaps next S)
        __syncthreads();
        if (kt + 1 < 16) ISSUE_V(kt + 1);
        cp_commit();
    }
    #undef ISSUE_K
    #undef ISSUE_V

    const int h = nh & 15;
    const int n = nh >> 4;
    const float hs = head_scale[h];
    const float sAf = hs / liA, sBf = hs / liB;
    const int lA = qt*64 + rA;
    const int lB = qt*64 + rB;
    #pragma unroll
    for (int j = 0; j < 8; j++) {
        const int col = h*HD + j*8 + 2*kq;
        *reinterpret_cast<float2*>(&g_o[(size_t)(lA*NB + n)*CC + col]) =
            make_float2(acc[j][0]*sAf, acc[j][1]*sAf);
        *reinterpret_cast<float2*>(&g_o[(size_t)(lB*NB + n)*CC + col]) =
            make_float2(acc[j][2]*sBf, acc[j][3]*sBf);
    }
}

// ============================================================
extern "C" void kernel_launch(void* const* d_in, const int* in_sizes, int n_in,
                              void* d_out, int out_size) {
    const float* x           = (const float*)d_in[0];
    const float* w_in        = (const float*)d_in[1];
    const float* b_in        = (const float*)d_in[2];
    const float* logit_scale = (const float*)d_in[3];
    const float* head_scale  = (const float*)d_in[4];
    const float* out_w       = (const float*)d_in[5];
    const float* out_b       = (const float*)d_in[6];
    float* out = (float*)d_out;

    float *qkv_p, *o_p, *xp_p, *op_p, *w1p_p, *w2p_p;
    cudaGetSymbolAddress((void**)&qkv_p, g_qkv);
    cudaGetSymbolAddress((void**)&o_p,   g_o);
    cudaGetSymbolAddress((void**)&xp_p,  g_xp);
    cudaGetSymbolAddress((void**)&op_p,  g_op);
    cudaGetSymbolAddress((void**)&w1p_p, g_w1p);
    cudaGetSymbolAddress((void**)&w2p_p, g_w2p);

    cudaFuncSetAttribute(flash_attn_mma,
                         cudaFuncAttributeMaxDynamicSharedMemorySize, FLASH_SMEM);
    cudaFuncSetAttribute(gemm_tf32_pk,
                         cudaFuncAttributeMaxDynamicSharedMemorySize, GEMM_SMEM);

    pack_a<<<MM, 256>>>(x, xp_p);
    pack_b<<<C3*2, 256>>>(w_in, w1p_p);
    pack_b<<<CC*2, 256>>>(out_w, w2p_p);

    // 1) qkv = x @ W^T + b
    gemm_tf32_pk<<<dim3(C3/128, MM/128), 256, GEMM_SMEM>>>(xp_p, w1p_p, b_in, qkv_p, C3);
    // 2) normalize + scatter (hi/lo split, tf32 pre-round, coalesced)
    norm_scatter_kernel<<<(3*NHH*LL)/8, 256>>>(logit_scale);
    // 3) flash attention (pipelined K/V copies)
    flash_attn_mma<<<dim3(LL/64, NHH), 128, FLASH_SMEM>>>(head_scale);
    // 4) out = o @ out_w^T + out_b
    pack_a<<<MM, 256>>>(o_p, op_p);
    gemm_tf32_pk<<<dim3(CC/128, MM/128), 256, GEMM_SMEM>>>(op_p, w2p_p, out_b, out, CC);
}

// round 10
// speedup vs baseline: 1.5432x; 1.1353x over previous
#include <cuda_runtime.h>
#include <math.h>
#include <stdint.h>

#define LL 1024
#define NB 8
#define CC 1024
#define HH 16
#define HD 64
#define MM (LL*NB)          // 8192
#define C3 (3*CC)           // 3072
#define NHH (NB*HH)         // 128
#define LOGIT_MAX 4.605170185988091f
#define KIT 64              // K=1024 -> 64 k16 stages

// ---- scratch (device globals) ----
__device__ float g_qkv[(size_t)MM * C3];
__device__ float g_q[(size_t)NHH * LL * 128];  // pair-float4 hi/lo rows
__device__ float g_k[(size_t)NHH * LL * 128];  // pair-float4 hi/lo rows
__device__ float g_v[(size_t)NHH * LL * HD];   // tf32-rounded
__device__ float g_o[(size_t)MM * CC];
__device__ float g_xp[(size_t)MM * CC];    // packed x
__device__ float g_op[(size_t)MM * CC];    // packed attn-out
__device__ float g_w1p[(size_t)C3 * CC];   // packed in_proj_weight
__device__ float g_w2p[(size_t)CC * CC];   // packed out_w

__device__ __forceinline__ float tf32r(float x) {
    uint32_t u;
    asm("cvt.rna.tf32.f32 %0, %1;" : "=r"(u) : "f"(x));
    return __uint_as_float(u);
}
__device__ __forceinline__ uint32_t smem_u32(const void* p) {
    uint32_t a;
    asm("{ .reg .u64 t; cvta.to.shared.u64 t, %1; cvt.u32.u64 %0, t; }" : "=r"(a) : "l"(p));
    return a;
}
__device__ __forceinline__ void cp16(uint32_t dst, const void* src) {
    asm volatile("cp.async.cg.shared.global [%0], [%1], 16;" :: "r"(dst), "l"(src));
}
__device__ __forceinline__ void cp_commit() {
    asm volatile("cp.async.commit_group;");
}
__device__ __forceinline__ void cp_wait2() {
    asm volatile("cp.async.wait_group 2;");
}
__device__ __forceinline__ void cp_wait1() {
    asm volatile("cp.async.wait_group 1;");
}
__device__ __forceinline__ void mma_tf32_16x8x8(float* d, const uint32_t* a, const uint32_t* b) {
    asm volatile(
        "mma.sync.aligned.m16n8k8.row.col.f32.tf32.tf32.f32 "
        "{%0,%1,%2,%3}, {%4,%5,%6,%7}, {%8,%9}, {%0,%1,%2,%3};\n"
        : "+f"(d[0]), "+f"(d[1]), "+f"(d[2]), "+f"(d[3])
        : "r"(a[0]), "r"(a[1]), "r"(a[2]), "r"(a[3]), "r"(b[0]), "r"(b[1]));
}

// ============================================================
// Pack A [M x 1024] row-major -> fragment-order tf32 stages.
// ============================================================
__global__ __launch_bounds__(256)
void pack_a(const float* __restrict__ src, float* __restrict__ dst) {
    const size_t d = (size_t)blockIdx.x * 256 + threadIdx.x;
    const int fi   = (int)(d & 511);
    const size_t sid = d >> 9;
    const int mb = (int)(sid >> 6);
    const int kb = (int)(sid & 63);
    const int c  = fi >> 8;
    const int mt = (fi >> 5) & 7;
    const int lane = fi & 31;
    const int g  = lane >> 2;
    const int kq = lane & 3;
    const int r0 = mb*128 + mt*16 + g;
    const int k0 = kb*16 + c*8 + kq;
    float4 o;
    o.x = tf32r(src[(size_t)r0      * 1024 + k0]);
    o.y = tf32r(src[(size_t)(r0+8)  * 1024 + k0]);
    o.z = tf32r(src[(size_t)r0      * 1024 + k0 + 4]);
    o.w = tf32r(src[(size_t)(r0+8)  * 1024 + k0 + 4]);
    reinterpret_cast<float4*>(dst)[d] = o;
}

// ============================================================
// Pack B [N x 1024] row-major -> fragment-order tf32 stages.
// ============================================================
__global__ __launch_bounds__(256)
void pack_b(const float* __restrict__ src, float* __restrict__ dst) {
    const size_t d = (size_t)blockIdx.x * 256 + threadIdx.x;
    const int fi   = (int)(d & 1023);
    const size_t sid = d >> 10;
    const int nb = (int)(sid >> 6);
    const int kb = (int)(sid & 63);
    const int c  = fi >> 9;
    const int nt = (fi >> 5) & 15;
    const int lane = fi & 31;
    const int g  = lane >> 2;
    const int kq = lane & 3;
    const int col = nb*128 + nt*8 + g;
    const int k0  = kb*16 + c*8 + kq;
    float2 o;
    o.x = tf32r(src[(size_t)col * 1024 + k0]);
    o.y = tf32r(src[(size_t)col * 1024 + k0 + 4]);
    reinterpret_cast<float2*>(dst)[d] = o;
}

// ============================================================
// tf32 mma.sync GEMM on packed operands (unchanged, passing).
// ============================================================
#define GEMM_SMEM (4*4096*4)

__global__ __launch_bounds__(256, 2)
void gemm_tf32_pk(const float* __restrict__ Ap, const float* __restrict__ Bp,
                  const float* __restrict__ bias, float* __restrict__ C,
                  int Ncols) {
    extern __shared__ float sm[];
    const uint32_t smb = smem_u32(sm);
    const int t  = threadIdx.x;
    const int wid  = t >> 5;
    const int lane = t & 31;
    const int g  = lane >> 2;
    const int kq = lane & 3;
    const int wm4 = (wid >> 2) * 4;
    const int wn8 = (wid & 3) * 4;
    const int m0 = blockIdx.y * 128;
    const int n0 = blockIdx.x * 128;

    const float* Ab = Ap + (size_t)blockIdx.y * KIT * 2048;
    const float* Bb = Bp + (size_t)blockIdx.x * KIT * 2048;

    float acc[4][4][4] = {};

    #define ISSUE(j)                                                        \
    {                                                                       \
        const uint32_t sb = smb + ((j) & 3) * 16384;                        \
        const float* ag = Ab + (size_t)(j) * 2048;                          \
        const float* bg = Bb + (size_t)(j) * 2048;                          \
        cp16(sb +            t*16, ag + t*4);                               \
        cp16(sb +  4096    + t*16, ag + 1024 + t*4);                        \
        cp16(sb +  8192    + t*16, bg + t*4);                               \
        cp16(sb + 12288    + t*16, bg + 1024 + t*4);                        \
    }

    ISSUE(0); cp_commit();
    ISSUE(1); cp_commit();
    ISSUE(2); cp_commit();

    for (int i = 0; i < KIT; i++) {
        cp_wait2();
        __syncthreads();
        const float* as = sm + (i & 3) * 4096;
        const float* bs = as + 2048;
        #pragma unroll
        for (int c = 0; c < 2; c++) {
            uint32_t a[4][4], b[4][2];
            #pragma unroll
            for (int ti = 0; ti < 4; ti++) {
                float4 af = *reinterpret_cast<const float4*>(
                    &as[(c*8 + wm4 + ti)*128 + lane*4]);
                a[ti][0] = __float_as_uint(af.x);
                a[ti][1] = __float_as_uint(af.y);
                a[ti][2] = __float_as_uint(af.z);
                a[ti][3] = __float_as_uint(af.w);
            }
            #pragma unroll
            for (int j = 0; j < 4; j++) {
                float2 bf = *reinterpret_cast<const float2*>(
                    &bs[(c*16 + wn8 + j)*64 + lane*2]);
                b[j][0] = __float_as_uint(bf.x);
                b[j][1] = __float_as_uint(bf.y);
            }
            #pragma unroll
            for (int ti = 0; ti < 4; ti++)
                #pragma unroll
                for (int j = 0; j < 4; j++)
                    mma_tf32_16x8x8(acc[ti][j], a[ti], b[j]);
        }
        const int jn = i + 3;
        if (jn < KIT) ISSUE(jn);
        cp_commit();
    }
    #undef ISSUE

    #pragma unroll
    for (int ti = 0; ti < 4; ti++) {
        const int r0 = m0 + wm4*16 + ti*16 + g;
        #pragma unroll
        for (int j = 0; j < 4; j++) {
            const int c0 = n0 + wn8*8 + j*8 + 2*kq;
            const float bx = bias[c0], by = bias[c0+1];
            float2 lo, hi;
            lo.x = acc[ti][j][0] + bx; lo.y = acc[ti][j][1] + by;
            hi.x = acc[ti][j][2] + bx; hi.y = acc[ti][j][3] + by;
            *reinterpret_cast<float2*>(&C[(size_t)r0 * Ncols + c0]) = lo;
            *reinterpret_cast<float2*>(&C[(size_t)(r0+8) * Ncols + c0]) = hi;
        }
    }
}

// ============================================================
// Normalize + scatter. Q,K rows written in PAIR-FLOAT4 layout:
// float4 slot p = kb*4+kq holds {hi(k), lo(k), hi(k+4), lo(k+4)},
// k = kb*8+kq. Partner hi/lo fetched via shfl_xor(4). V unchanged.
// ============================================================
__global__ __launch_bounds__(256)
void norm_scatter_kernel(const float* __restrict__ logit_scale) {
    const int warp = (blockIdx.x * blockDim.x + threadIdx.x) >> 5;
    const int lane = threadIdx.x & 31;
    const int tsel = warp / (NHH * LL);
    const int rr   = warp - tsel * (NHH * LL);
    const int nh   = rr >> 10;
    const int l    = rr & 1023;
    const int n    = nh >> 4;
    const int h    = nh & 15;
    const size_t src = (size_t)(l * NB + n) * C3 + (size_t)tsel * CC + h * HD;
    float v0 = g_qkv[src + lane];
    float v1 = g_qkv[src + lane + 32];
    if (tsel < 2) {
        float s = v0*v0 + v1*v1;
        #pragma unroll
        for (int o = 16; o > 0; o >>= 1) s += __shfl_xor_sync(0xffffffffu, s, o);
        float inv = 1.0f / fmaxf(sqrtf(s), 1e-12f);
        if (tsel == 0) inv *= expf(fminf(logit_scale[h], LOGIT_MAX));
        v0 *= inv; v1 *= inv;
        float hi0 = tf32r(v0), lo0 = tf32r(v0 - hi0);
        float hi1 = tf32r(v1), lo1 = tf32r(v1 - hi1);
        float hi0p = __shfl_xor_sync(0xffffffffu, hi0, 4);
        float lo0p = __shfl_xor_sync(0xffffffffu, lo0, 4);
        float hi1p = __shfl_xor_sync(0xffffffffu, hi1, 4);
        float lo1p = __shfl_xor_sync(0xffffffffu, lo1, 4);
        if ((lane & 4) == 0) {
            const int p0 = (lane >> 3) * 4 + (lane & 3);
            float4* row = reinterpret_cast<float4*>(
                (tsel == 0 ? g_q : g_k) + ((size_t)nh * LL + l) * 128);
            row[p0]      = make_float4(hi0, lo0, hi0p, lo0p);
            row[p0 + 16] = make_float4(hi1, lo1, hi1p, lo1p);
        }
    } else {
        const size_t o = ((size_t)nh * LL + l) * HD;
        g_v[o + lane]      = tf32r(v0);
        g_v[o + lane + 32] = tf32r(v1);
    }
}

// ============================================================
// Flash attention v2: Q fragments in registers, K pair-float4
// smem (stride 144, conflict-free LDS.128), 3 CTAs/SM.
// ============================================================
#define KSTR 144
#define VSTR 72
#define PSTR 72
#define FL_K 0
#define FL_V (64*KSTR)
#define FL_P (64*KSTR + 64*VSTR)
#define FLASH_SMEM ((64*KSTR + 64*VSTR + 64*PSTR) * (int)sizeof(float))   // 73728

__global__ __launch_bounds__(128, 3)
void flash_attn_mma(const float* __restrict__ head_scale) {
    extern __shared__ float smf[];
    float* Ks = smf + FL_K;
    float* Vs = smf + FL_V;
    float* Ps = smf + FL_P;
    const uint32_t smbK = smem_u32(smf) + FL_K * 4;
    const uint32_t smbV = smem_u32(smf) + FL_V * 4;

    const int t    = threadIdx.x;
    const int w    = t >> 5;
    const int lane = t & 31;
    const int g    = lane >> 2;
    const int kq   = lane & 3;
    const int nh = blockIdx.y;
    const int qt = blockIdx.x;
    const float* Kg = g_k + (size_t)nh * LL * 128;
    const float* Vg = g_v + (size_t)nh * LL * HD;

    const int rA = w*16 + g;
    const int rB = rA + 8;

    #define ISSUE_K(kt)                                                     \
    {                                                                       \
        const float* Kt = Kg + (size_t)(kt) * 64 * 128;                     \
        for (int i = t; i < 2048; i += 128) {                               \
            int r = i >> 5, c = i & 31;                                     \
            cp16(smbK + r*(KSTR*4) + c*16, Kt + r*128 + c*4);               \
        }                                                                   \
    }
    #define ISSUE_V(kt)                                                     \
    {                                                                       \
        const float* Vt = Vg + (size_t)(kt) * 64 * 64;                      \
        for (int i = t; i < 1024; i += 128) {                               \
            int r = i >> 4, c = i & 15;                                     \
            cp16(smbV + r*(VSTR*4) + c*16, Vt + r*64 + c*4);                \
        }                                                                   \
    }

    ISSUE_K(0); cp_commit();
    ISSUE_V(0); cp_commit();

    // Q fragments -> registers (pair-float4 rows in gmem)
    uint32_t ah[8][4], al[8][4];
    {
        const float4* Qg4 = reinterpret_cast<const float4*>(
            g_q + ((size_t)nh * LL + qt * 64) * 128);
        #pragma unroll
        for (int kb = 0; kb < 8; kb++) {
            float4 fA = Qg4[rA*32 + kb*4 + kq];
            float4 fB = Qg4[rB*32 + kb*4 + kq];
            ah[kb][0] = __float_as_uint(fA.x);
            ah[kb][1] = __float_as_uint(fB.x);
            ah[kb][2] = __float_as_uint(fA.z);
            ah[kb][3] = __float_as_uint(fB.z);
            al[kb][0] = __float_as_uint(fA.y);
            al[kb][1] = __float_as_uint(fB.y);
            al[kb][2] = __float_as_uint(fA.w);
            al[kb][3] = __float_as_uint(fB.w);
        }
    }

    float acc[8][4] = {};
    float miA = -1e30f, miB = -1e30f, liA = 0.0f, liB = 0.0f;

    for (int kt = 0; kt < 16; kt++) {
        // K_kt ready (V_kt may be in flight)
        cp_wait1();
        __syncthreads();

        // ---- S = Q @ K^T (3xTF32) ----
        float sd[8][4] = {};
        #pragma unroll
        for (int kb = 0; kb < 8; kb++) {
            #pragma unroll
            for (int j = 0; j < 8; j++) {
                float4 f4 = *reinterpret_cast<const float4*>(
                    &Ks[(j*8 + g)*KSTR + (kb*4 + kq)*4]);
                uint32_t bhi[2] = {__float_as_uint(f4.x), __float_as_uint(f4.z)};
                uint32_t blo[2] = {__float_as_uint(f4.y), __float_as_uint(f4.w)};
                mma_tf32_16x8x8(sd[j], ah[kb], bhi);
                mma_tf32_16x8x8(sd[j], ah[kb], blo);
                mma_tf32_16x8x8(sd[j], al[kb], bhi);
            }
        }

        // ---- online softmax ----
        float rmA = -1e30f, rmB = -1e30f;
        #pragma unroll
        for (int j = 0; j < 8; j++) {
            rmA = fmaxf(rmA, fmaxf(sd[j][0], sd[j][1]));
            rmB = fmaxf(rmB, fmaxf(sd[j][2], sd[j][3]));
        }
        rmA = fmaxf(rmA, __shfl_xor_sync(0xffffffffu, rmA, 1));
        rmA = fmaxf(rmA, __shfl_xor_sync(0xffffffffu, rmA, 2));
        rmB = fmaxf(rmB, __shfl_xor_sync(0xffffffffu, rmB, 1));
        rmB = fmaxf(rmB, __shfl_xor_sync(0xffffffffu, rmB, 2));
        float mA = fmaxf(miA, rmA), mB = fmaxf(miB, rmB);
        float corrA = __expf(miA - mA), corrB = __expf(miB - mB);
        float sumA = 0.0f, sumB = 0.0f;
        #pragma unroll
        for (int j = 0; j < 8; j++) {
            float p0 = __expf(sd[j][0] - mA);
            float p1 = __expf(sd[j][1] - mA);
            float p2 = __expf(sd[j][2] - mB);
            float p3 = __expf(sd[j][3] - mB);
            sumA += p0 + p1;
            sumB += p2 + p3;
            *reinterpret_cast<float2*>(&Ps[rA*PSTR + j*8 + 2*kq]) =
                make_float2(tf32r(p0), tf32r(p1));
            *reinterpret_cast<float2*>(&Ps[rB*PSTR + j*8 + 2*kq]) =
                make_float2(tf32r(p2), tf32r(p3));
            acc[j][0] *= corrA; acc[j][1] *= corrA;
            acc[j][2] *= corrB; acc[j][3] *= corrB;
        }
        sumA += __shfl_xor_sync(0xffffffffu, sumA, 1);
        sumA += __shfl_xor_sync(0xffffffffu, sumA, 2);
        sumB += __shfl_xor_sync(0xffffffffu, sumB, 1);
        sumB += __shfl_xor_sync(0xffffffffu, sumB, 2);
        liA = liA * corrA + sumA;  miA = mA;
        liB = liB * corrB + sumB;  miB = mB;

        // Ks dead -> start K_{kt+1} copy (overlaps V-wait + PV)
        __syncthreads();
        if (kt + 1 < 16) ISSUE_K(kt + 1);
        cp_commit();

        // V_kt ready
        cp_wait1();
        __syncthreads();

        // ---- O += P @ V (single tf32) ----
        #pragma unroll
        for (int kb = 0; kb < 8; kb++) {
            uint32_t pa[4];
            pa[0] = __float_as_uint(Ps[rA*PSTR + kb*8+kq]);
            pa[1] = __float_as_uint(Ps[rB*PSTR + kb*8+kq]);
            pa[2] = __float_as_uint(Ps[rA*PSTR + kb*8+kq+4]);
            pa[3] = __float_as_uint(Ps[rB*PSTR + kb*8+kq+4]);
            #pragma unroll
            for (int j = 0; j < 8; j++) {
                uint32_t vb[2];
                vb[0] = __float_as_uint(Vs[(kb*8+kq)*VSTR   + j*8+g]);
                vb[1] = __float_as_uint(Vs[(kb*8+kq+4)*VSTR + j*8+g]);
                mma_tf32_16x8x8(acc[j], pa, vb);
            }
        }

        // Vs dead -> start V_{kt+1} copy (overlaps next S)
        __syncthreads();
        if (kt + 1 < 16) ISSUE_V(kt + 1);
        cp_commit();
    }
    #undef ISSUE_K
    #undef ISSUE_V

    const int h = nh & 15;
    const int n = nh >> 4;
    const float hs = head_scale[h];
    const float sAf = hs / liA, sBf = hs / liB;
    const int lA = qt*64 + rA;
    const int lB = qt*64 + rB;
    #pragma unroll
    for (int j = 0; j < 8; j++) {
        const int col = h*HD + j*8 + 2*kq;
        *reinterpret_cast<float2*>(&g_o[(size_t)(lA*NB + n)*CC + col]) =
            make_float2(acc[j][0]*sAf, acc[j][1]*sAf);
        *reinterpret_cast<float2*>(&g_o[(size_t)(lB*NB + n)*CC + col]) =
            make_float2(acc[j][2]*sBf, acc[j][3]*sBf);
    }
}

// ============================================================
extern "C" void kernel_launch(void* const* d_in, const int* in_sizes, int n_in,
                              void* d_out, int out_size) {
    const float* x           = (const float*)d_in[0];
    const float* w_in        = (const float*)d_in[1];
    const float* b_in        = (const float*)d_in[2];
    const float* logit_scale = (const float*)d_in[3];
    const float* head_scale  = (const float*)d_in[4];
    const float* out_w       = (const float*)d_in[5];
    const float* out_b       = (const float*)d_in[6];
    float* out = (float*)d_out;

    float *qkv_p, *o_p, *xp_p, *op_p, *w1p_p, *w2p_p;
    cudaGetSymbolAddress((void**)&qkv_p, g_qkv);
    cudaGetSymbolAddress((void**)&o_p,   g_o);
    cudaGetSymbolAddress((void**)&xp_p,  g_xp);
    cudaGetSymbolAddress((void**)&op_p,  g_op);
    cudaGetSymbolAddress((void**)&w1p_p, g_w1p);
    cudaGetSymbolAddress((void**)&w2p_p, g_w2p);

    cudaFuncSetAttribute(flash_attn_mma,
                         cudaFuncAttributeMaxDynamicSharedMemorySize, FLASH_SMEM);
    cudaFuncSetAttribute(gemm_tf32_pk,
                         cudaFuncAttributeMaxDynamicSharedMemorySize, GEMM_SMEM);

    pack_a<<<MM, 256>>>(x, xp_p);
    pack_b<<<C3*2, 256>>>(w_in, w1p_p);
    pack_b<<<CC*2, 256>>>(out_w, w2p_p);

    // 1) qkv = x @ W^T + b
    gemm_tf32_pk<<<dim3(C3/128, MM/128), 256, GEMM_SMEM>>>(xp_p, w1p_p, b_in, qkv_p, C3);
    // 2) normalize + scatter (pair-float4 q/k, tf32 v)
    norm_scatter_kernel<<<(3*NHH*LL)/8, 256>>>(logit_scale);
    // 3) flash attention (Q-in-regs, 3 CTAs/SM)
    flash_attn_mma<<<dim3(LL/64, NHH), 128, FLASH_SMEM>>>(head_scale);
    // 4) out = o @ out_w^T + out_b
    pack_a<<<MM, 256>>>(o_p, op_p);
    gemm_tf32_pk<<<dim3(CC/128, MM/128), 256, GEMM_SMEM>>>(op_p, w2p_p, out_b, out, CC);
}

// round 11
// speedup vs baseline: 1.5595x; 1.0106x over previous
#include <cuda_runtime.h>
#include <math.h>
#include <stdint.h>

#define LL 1024
#define NB 8
#define CC 1024
#define HH 16
#define HD 64
#define MM (LL*NB)          // 8192
#define C3 (3*CC)           // 3072
#define NHH (NB*HH)         // 128
#define LOGIT_MAX 4.605170185988091f
#define KIT 64              // K=1024 -> 64 k16 stages

// ---- scratch (device globals) ----
__device__ float g_qkv[(size_t)MM * C3];
__device__ float g_q[(size_t)NHH * LL * 128];  // pair-float4 hi/lo rows
__device__ float g_k[(size_t)NHH * LL * 128];  // pair-float4 hi/lo rows
__device__ float g_v[(size_t)NHH * LL * HD];   // tf32-rounded
__device__ float g_o[(size_t)MM * CC];
__device__ float g_xp[(size_t)MM * CC];    // packed x
__device__ float g_op[(size_t)MM * CC];    // packed attn-out
__device__ float g_w1p[(size_t)C3 * CC];   // packed in_proj_weight
__device__ float g_w2p[(size_t)CC * CC];   // packed out_w

__device__ __forceinline__ float tf32r(float x) {
    uint32_t u;
    asm("cvt.rna.tf32.f32 %0, %1;" : "=r"(u) : "f"(x));
    return __uint_as_float(u);
}
__device__ __forceinline__ uint32_t smem_u32(const void* p) {
    uint32_t a;
    asm("{ .reg .u64 t; cvta.to.shared.u64 t, %1; cvt.u32.u64 %0, t; }" : "=r"(a) : "l"(p));
    return a;
}
__device__ __forceinline__ void cp16(uint32_t dst, const void* src) {
    asm volatile("cp.async.cg.shared.global [%0], [%1], 16;" :: "r"(dst), "l"(src));
}
__device__ __forceinline__ void cp_commit() {
    asm volatile("cp.async.commit_group;");
}
__device__ __forceinline__ void cp_wait2() {
    asm volatile("cp.async.wait_group 2;");
}
__device__ __forceinline__ void cp_wait1() {
    asm volatile("cp.async.wait_group 1;");
}
__device__ __forceinline__ void mma_tf32_16x8x8(float* d, const uint32_t* a, const uint32_t* b) {
    asm volatile(
        "mma.sync.aligned.m16n8k8.row.col.f32.tf32.tf32.f32 "
        "{%0,%1,%2,%3}, {%4,%5,%6,%7}, {%8,%9}, {%0,%1,%2,%3};\n"
        : "+f"(d[0]), "+f"(d[1]), "+f"(d[2]), "+f"(d[3])
        : "r"(a[0]), "r"(a[1]), "r"(a[2]), "r"(a[3]), "r"(b[0]), "r"(b[1]));
}

// ============================================================
// Pack A [M x 1024] row-major -> fragment-order tf32 stages.
// ============================================================
__global__ __launch_bounds__(256)
void pack_a(const float* __restrict__ src, float* __restrict__ dst) {
    const size_t d = (size_t)blockIdx.x * 256 + threadIdx.x;
    const int fi   = (int)(d & 511);
    const size_t sid = d >> 9;
    const int mb = (int)(sid >> 6);
    const int kb = (int)(sid & 63);
    const int c  = fi >> 8;
    const int mt = (fi >> 5) & 7;
    const int lane = fi & 31;
    const int g  = lane >> 2;
    const int kq = lane & 3;
    const int r0 = mb*128 + mt*16 + g;
    const int k0 = kb*16 + c*8 + kq;
    float4 o;
    o.x = tf32r(src[(size_t)r0      * 1024 + k0]);
    o.y = tf32r(src[(size_t)(r0+8)  * 1024 + k0]);
    o.z = tf32r(src[(size_t)r0      * 1024 + k0 + 4]);
    o.w = tf32r(src[(size_t)(r0+8)  * 1024 + k0 + 4]);
    reinterpret_cast<float4*>(dst)[d] = o;
}

// ============================================================
// Pack B [N x 1024] row-major -> fragment-order tf32 stages.
// ============================================================
__global__ __launch_bounds__(256)
void pack_b(const float* __restrict__ src, float* __restrict__ dst) {
    const size_t d = (size_t)blockIdx.x * 256 + threadIdx.x;
    const int fi   = (int)(d & 1023);
    const size_t sid = d >> 10;
    const int nb = (int)(sid >> 6);
    const int kb = (int)(sid & 63);
    const int c  = fi >> 9;
    const int nt = (fi >> 5) & 15;
    const int lane = fi & 31;
    const int g  = lane >> 2;
    const int kq = lane & 3;
    const int col = nb*128 + nt*8 + g;
    const int k0  = kb*16 + c*8 + kq;
    float2 o;
    o.x = tf32r(src[(size_t)col * 1024 + k0]);
    o.y = tf32r(src[(size_t)col * 1024 + k0 + 4]);
    reinterpret_cast<float2*>(dst)[d] = o;
}

// ============================================================
// tf32 mma.sync GEMM on packed operands (unchanged, passing).
// ============================================================
#define GEMM_SMEM (4*4096*4)

__global__ __launch_bounds__(256, 2)
void gemm_tf32_pk(const float* __restrict__ Ap, const float* __restrict__ Bp,
                  const float* __restrict__ bias, float* __restrict__ C,
                  int Ncols) {
    extern __shared__ float sm[];
    const uint32_t smb = smem_u32(sm);
    const int t  = threadIdx.x;
    const int wid  = t >> 5;
    const int lane = t & 31;
    const int g  = lane >> 2;
    const int kq = lane & 3;
    const int wm4 = (wid >> 2) * 4;
    const int wn8 = (wid & 3) * 4;
    const int m0 = blockIdx.y * 128;
    const int n0 = blockIdx.x * 128;

    const float* Ab = Ap + (size_t)blockIdx.y * KIT * 2048;
    const float* Bb = Bp + (size_t)blockIdx.x * KIT * 2048;

    float acc[4][4][4] = {};

    #define ISSUE(j)                                                        \
    {                                                                       \
        const uint32_t sb = smb + ((j) & 3) * 16384;                        \
        const float* ag = Ab + (size_t)(j) * 2048;                          \
        const float* bg = Bb + (size_t)(j) * 2048;                          \
        cp16(sb +            t*16, ag + t*4);                               \
        cp16(sb +  4096    + t*16, ag + 1024 + t*4);                        \
        cp16(sb +  8192    + t*16, bg + t*4);                               \
        cp16(sb + 12288    + t*16, bg + 1024 + t*4);                        \
    }

    ISSUE(0); cp_commit();
    ISSUE(1); cp_commit();
    ISSUE(2); cp_commit();

    for (int i = 0; i < KIT; i++) {
        cp_wait2();
        __syncthreads();
        const float* as = sm + (i & 3) * 4096;
        const float* bs = as + 2048;
        #pragma unroll
        for (int c = 0; c < 2; c++) {
            uint32_t a[4][4], b[4][2];
            #pragma unroll
            for (int ti = 0; ti < 4; ti++) {
                float4 af = *reinterpret_cast<const float4*>(
                    &as[(c*8 + wm4 + ti)*128 + lane*4]);
                a[ti][0] = __float_as_uint(af.x);
                a[ti][1] = __float_as_uint(af.y);
                a[ti][2] = __float_as_uint(af.z);
                a[ti][3] = __float_as_uint(af.w);
            }
            #pragma unroll
            for (int j = 0; j < 4; j++) {
                float2 bf = *reinterpret_cast<const float2*>(
                    &bs[(c*16 + wn8 + j)*64 + lane*2]);
                b[j][0] = __float_as_uint(bf.x);
                b[j][1] = __float_as_uint(bf.y);
            }
            #pragma unroll
            for (int ti = 0; ti < 4; ti++)
                #pragma unroll
                for (int j = 0; j < 4; j++)
                    mma_tf32_16x8x8(acc[ti][j], a[ti], b[j]);
        }
        const int jn = i + 3;
        if (jn < KIT) ISSUE(jn);
        cp_commit();
    }
    #undef ISSUE

    #pragma unroll
    for (int ti = 0; ti < 4; ti++) {
        const int r0 = m0 + wm4*16 + ti*16 + g;
        #pragma unroll
        for (int j = 0; j < 4; j++) {
            const int c0 = n0 + wn8*8 + j*8 + 2*kq;
            const float bx = bias[c0], by = bias[c0+1];
            float2 lo, hi;
            lo.x = acc[ti][j][0] + bx; lo.y = acc[ti][j][1] + by;
            hi.x = acc[ti][j][2] + bx; hi.y = acc[ti][j][3] + by;
            *reinterpret_cast<float2*>(&C[(size_t)r0 * Ncols + c0]) = lo;
            *reinterpret_cast<float2*>(&C[(size_t)(r0+8) * Ncols + c0]) = hi;
        }
    }
}

// ============================================================
// Normalize + scatter (pair-float4 q/k, tf32 v; unchanged).
// ============================================================
__global__ __launch_bounds__(256)
void norm_scatter_kernel(const float* __restrict__ logit_scale) {
    const int warp = (blockIdx.x * blockDim.x + threadIdx.x) >> 5;
    const int lane = threadIdx.x & 31;
    const int tsel = warp / (NHH * LL);
    const int rr   = warp - tsel * (NHH * LL);
    const int nh   = rr >> 10;
    const int l    = rr & 1023;
    const int n    = nh >> 4;
    const int h    = nh & 15;
    const size_t src = (size_t)(l * NB + n) * C3 + (size_t)tsel * CC + h * HD;
    float v0 = g_qkv[src + lane];
    float v1 = g_qkv[src + lane + 32];
    if (tsel < 2) {
        float s = v0*v0 + v1*v1;
        #pragma unroll
        for (int o = 16; o > 0; o >>= 1) s += __shfl_xor_sync(0xffffffffu, s, o);
        float inv = 1.0f / fmaxf(sqrtf(s), 1e-12f);
        if (tsel == 0) inv *= expf(fminf(logit_scale[h], LOGIT_MAX));
        v0 *= inv; v1 *= inv;
        float hi0 = tf32r(v0), lo0 = tf32r(v0 - hi0);
        float hi1 = tf32r(v1), lo1 = tf32r(v1 - hi1);
        float hi0p = __shfl_xor_sync(0xffffffffu, hi0, 4);
        float lo0p = __shfl_xor_sync(0xffffffffu, lo0, 4);
        float hi1p = __shfl_xor_sync(0xffffffffu, hi1, 4);
        float lo1p = __shfl_xor_sync(0xffffffffu, lo1, 4);
        if ((lane & 4) == 0) {
            const int p0 = (lane >> 3) * 4 + (lane & 3);
            float4* row = reinterpret_cast<float4*>(
                (tsel == 0 ? g_q : g_k) + ((size_t)nh * LL + l) * 128);
            row[p0]      = make_float4(hi0, lo0, hi0p, lo0p);
            row[p0 + 16] = make_float4(hi1, lo1, hi1p, lo1p);
        }
    } else {
        const size_t o = ((size_t)nh * LL + l) * HD;
        g_v[o + lane]      = tf32r(v0);
        g_v[o + lane + 32] = tf32r(v1);
    }
}

// ============================================================
// Flash attention v3: Q-in-regs, pair-float4 K, 3 CTAs/SM,
// STATIC-MAX softmax: since |q̂·k̂| <= 1, S <= ls, so p = exp(S - ls)
// needs no running max, no correction, no acc rescale.
// ============================================================
#define KSTR 144
#define VSTR 72
#define PSTR 72
#define FL_K 0
#define FL_V (64*KSTR)
#define FL_P (64*KSTR + 64*VSTR)
#define FLASH_SMEM ((64*KSTR + 64*VSTR + 64*PSTR) * (int)sizeof(float))   // 73728

__global__ __launch_bounds__(128, 3)
void flash_attn_mma(const float* __restrict__ head_scale,
                    const float* __restrict__ logit_scale) {
    extern __shared__ float smf[];
    float* Ks = smf + FL_K;
    float* Vs = smf + FL_V;
    float* Ps = smf + FL_P;
    const uint32_t smbK = smem_u32(smf) + FL_K * 4;
    const uint32_t smbV = smem_u32(smf) + FL_V * 4;

    const int t    = threadIdx.x;
    const int w    = t >> 5;
    const int lane = t & 31;
    const int g    = lane >> 2;
    const int kq   = lane & 3;
    const int nh = blockIdx.y;
    const int qt = blockIdx.x;
    const int h  = nh & 15;
    const float* Kg = g_k + (size_t)nh * LL * 128;
    const float* Vg = g_v + (size_t)nh * LL * HD;
    const float mfix = expf(fminf(logit_scale[h], LOGIT_MAX));  // S <= mfix

    const int rA = w*16 + g;
    const int rB = rA + 8;

    #define ISSUE_K(kt)                                                     \
    {                                                                       \
        const float* Kt = Kg + (size_t)(kt) * 64 * 128;                     \
        for (int i = t; i < 2048; i += 128) {                               \
            int r = i >> 5, c = i & 31;                                     \
            cp16(smbK + r*(KSTR*4) + c*16, Kt + r*128 + c*4);               \
        }                                                                   \
    }
    #define ISSUE_V(kt)                                                     \
    {                                                                       \
        const float* Vt = Vg + (size_t)(kt) * 64 * 64;                      \
        for (int i = t; i < 1024; i += 128) {                               \
            int r = i >> 4, c = i & 15;                                     \
            cp16(smbV + r*(VSTR*4) + c*16, Vt + r*64 + c*4);                \
        }                                                                   \
    }

    ISSUE_K(0); cp_commit();
    ISSUE_V(0); cp_commit();

    // Q fragments -> registers (pair-float4 rows in gmem)
    uint32_t ah[8][4], al[8][4];
    {
        const float4* Qg4 = reinterpret_cast<const float4*>(
            g_q + ((size_t)nh * LL + qt * 64) * 128);
        #pragma unroll
        for (int kb = 0; kb < 8; kb++) {
            float4 fA = Qg4[rA*32 + kb*4 + kq];
            float4 fB = Qg4[rB*32 + kb*4 + kq];
            ah[kb][0] = __float_as_uint(fA.x);
            ah[kb][1] = __float_as_uint(fB.x);
            ah[kb][2] = __float_as_uint(fA.z);
            ah[kb][3] = __float_as_uint(fB.z);
            al[kb][0] = __float_as_uint(fA.y);
            al[kb][1] = __float_as_uint(fB.y);
            al[kb][2] = __float_as_uint(fA.w);
            al[kb][3] = __float_as_uint(fB.w);
        }
    }

    float acc[8][4] = {};
    float liA = 0.0f, liB = 0.0f;

    for (int kt = 0; kt < 16; kt++) {
        // K_kt ready (V_kt may be in flight)
        cp_wait1();
        __syncthreads();

        // ---- S = Q @ K^T (3xTF32) ----
        float sd[8][4] = {};
        #pragma unroll
        for (int kb = 0; kb < 8; kb++) {
            #pragma unroll
            for (int j = 0; j < 8; j++) {
                float4 f4 = *reinterpret_cast<const float4*>(
                    &Ks[(j*8 + g)*KSTR + (kb*4 + kq)*4]);
                uint32_t bhi[2] = {__float_as_uint(f4.x), __float_as_uint(f4.z)};
                uint32_t blo[2] = {__float_as_uint(f4.y), __float_as_uint(f4.w)};
                mma_tf32_16x8x8(sd[j], ah[kb], bhi);
                mma_tf32_16x8x8(sd[j], ah[kb], blo);
                mma_tf32_16x8x8(sd[j], al[kb], bhi);
            }
        }

        // ---- static-max softmax: p = exp(S - mfix) ----
        float sumA = 0.0f, sumB = 0.0f;
        #pragma unroll
        for (int j = 0; j < 8; j++) {
            float p0 = __expf(sd[j][0] - mfix);
            float p1 = __expf(sd[j][1] - mfix);
            float p2 = __expf(sd[j][2] - mfix);
            float p3 = __expf(sd[j][3] - mfix);
            sumA += p0 + p1;
            sumB += p2 + p3;
            *reinterpret_cast<float2*>(&Ps[rA*PSTR + j*8 + 2*kq]) =
                make_float2(tf32r(p0), tf32r(p1));
            *reinterpret_cast<float2*>(&Ps[rB*PSTR + j*8 + 2*kq]) =
                make_float2(tf32r(p2), tf32r(p3));
        }
        sumA += __shfl_xor_sync(0xffffffffu, sumA, 1);
        sumA += __shfl_xor_sync(0xffffffffu, sumA, 2);
        sumB += __shfl_xor_sync(0xffffffffu, sumB, 1);
        sumB += __shfl_xor_sync(0xffffffffu, sumB, 2);
        liA += sumA;
        liB += sumB;

        // Ks dead -> start K_{kt+1} copy (overlaps V-wait + PV)
        __syncthreads();
        if (kt + 1 < 16) ISSUE_K(kt + 1);
        cp_commit();

        // V_kt ready
        cp_wait1();
        __syncthreads();

        // ---- O += P @ V (single tf32) ----
        #pragma unroll
        for (int kb = 0; kb < 8; kb++) {
            uint32_t pa[4];
            pa[0] = __float_as_uint(Ps[rA*PSTR + kb*8+kq]);
            pa[1] = __float_as_uint(Ps[rB*PSTR + kb*8+kq]);
            pa[2] = __float_as_uint(Ps[rA*PSTR + kb*8+kq+4]);
            pa[3] = __float_as_uint(Ps[rB*PSTR + kb*8+kq+4]);
            #pragma unroll
            for (int j = 0; j < 8; j++) {
                uint32_t vb[2];
                vb[0] = __float_as_uint(Vs[(kb*8+kq)*VSTR   + j*8+g]);
                vb[1] = __float_as_uint(Vs[(kb*8+kq+4)*VSTR + j*8+g]);
                mma_tf32_16x8x8(acc[j], pa, vb);
            }
        }

        // Vs dead -> start V_{kt+1} copy (overlaps next S)
        __syncthreads();
        if (kt + 1 < 16) ISSUE_V(kt + 1);
        cp_commit();
    }
    #undef ISSUE_K
    #undef ISSUE_V

    const int n = nh >> 4;
    const float hs = head_scale[h];
    const float sAf = hs / liA, sBf = hs / liB;
    const int lA = qt*64 + rA;
    const int lB = qt*64 + rB;
    #pragma unroll
    for (int j = 0; j < 8; j++) {
        const int col = h*HD + j*8 + 2*kq;
        *reinterpret_cast<float2*>(&g_o[(size_t)(lA*NB + n)*CC + col]) =
            make_float2(acc[j][0]*sAf, acc[j][1]*sAf);
        *reinterpret_cast<float2*>(&g_o[(size_t)(lB*NB + n)*CC + col]) =
            make_float2(acc[j][2]*sBf, acc[j][3]*sBf);
    }
}

// ============================================================
extern "C" void kernel_launch(void* const* d_in, const int* in_sizes, int n_in,
                              void* d_out, int out_size) {
    const float* x           = (const float*)d_in[0];
    const float* w_in        = (const float*)d_in[1];
    const float* b_in        = (const float*)d_in[2];
    const float* logit_scale = (const float*)d_in[3];
    const float* head_scale  = (const float*)d_in[4];
    const float* out_w       = (const float*)d_in[5];
    const float* out_b       = (const float*)d_in[6];
    float* out = (float*)d_out;

    float *qkv_p, *o_p, *xp_p, *op_p, *w1p_p, *w2p_p;
    cudaGetSymbolAddress((void**)&qkv_p, g_qkv);
    cudaGetSymbolAddress((void**)&o_p,   g_o);
    cudaGetSymbolAddress((void**)&xp_p,  g_xp);
    cudaGetSymbolAddress((void**)&op_p,  g_op);
    cudaGetSymbolAddress((void**)&w1p_p, g_w1p);
    cudaGetSymbolAddress((void**)&w2p_p, g_w2p);

    cudaFuncSetAttribute(flash_attn_mma,
                         cudaFuncAttributeMaxDynamicSharedMemorySize, FLASH_SMEM);
    cudaFuncSetAttribute(gemm_tf32_pk,
                         cudaFuncAttributeMaxDynamicSharedMemorySize, GEMM_SMEM);

    pack_a<<<MM, 256>>>(x, xp_p);
    pack_b<<<C3*2, 256>>>(w_in, w1p_p);
    pack_b<<<CC*2, 256>>>(out_w, w2p_p);

    // 1) qkv = x @ W^T + b
    gemm_tf32_pk<<<dim3(C3/128, MM/128), 256, GEMM_SMEM>>>(xp_p, w1p_p, b_in, qkv_p, C3);
    // 2) normalize + scatter
    norm_scatter_kernel<<<(3*NHH*LL)/8, 256>>>(logit_scale);
    // 3) flash attention (static-max softmax)
    flash_attn_mma<<<dim3(LL/64, NHH), 128, FLASH_SMEM>>>(head_scale, logit_scale);
    // 4) out = o @ out_w^T + out_b
    pack_a<<<MM, 256>>>(o_p, op_p);
    gemm_tf32_pk<<<dim3(CC/128, MM/128), 256, GEMM_SMEM>>>(op_p, w2p_p, out_b, out, CC);
}